// round 3
// baseline (speedup 1.0000x reference)
#include <cuda_runtime.h>
#include <cstdint>

// ---------------- problem constants ----------------
namespace {
constexpr int kB   = 64;
constexpr int kD   = 256;
constexpr int kNS  = 8;
constexpr int kNT  = 1024;            // RES*RES
constexpr int kRows = kB * kNT;       // 65536 encoder rows
constexpr int kSR   = kB * kNS;       // 512 slot rows
constexpr float kScale = 0.0625f;     // 256^-0.5
constexpr float kEpsA  = 1e-8f;
constexpr float kEpsLN = 1e-5f;
}

// ---------------- scratch (device globals; no allocation) ----------------
__device__ float g_t[kRows * kD];
__device__ float g_f[kRows * kD];
__device__ float g_k[kRows * kD];
__device__ float g_v[kRows * kD];
__device__ float g_part[kB * 256 * 2];
__device__ float g_stats[kB * 2];
__device__ float g_slots[kSR * kD];
__device__ float g_sln[kSR * kD];
__device__ float g_q[kSR * kD];
__device__ float g_attn[kB * kNT * kNS];   // [b][tok][slot]
__device__ float g_rsp[kB * 8 * kNS];      // rowsum partials
__device__ float g_upd[kSR * kD];
__device__ float g_gi[kSR * 3 * kD];
__device__ float g_gh[kSR * 3 * kD];
__device__ float g_ns[kSR * kD];
__device__ float g_lnns[kSR * kD];
__device__ float g_h[kSR * kD];

// ---------------- tf32 helpers ----------------
__device__ __forceinline__ uint32_t f2tf32(float v) {
  uint32_t r;
  asm("cvt.rna.tf32.f32 %0, %1;" : "=r"(r) : "f"(v));
  return r;
}

__device__ __forceinline__ void mma8(float* c, const uint32_t* a, const uint32_t* b) {
  asm volatile(
      "mma.sync.aligned.m16n8k8.row.col.f32.tf32.tf32.f32 "
      "{%0,%1,%2,%3}, {%4,%5,%6,%7}, {%8,%9}, {%0,%1,%2,%3};\n"
      : "+f"(c[0]), "+f"(c[1]), "+f"(c[2]), "+f"(c[3])
      : "r"(a[0]), "r"(a[1]), "r"(a[2]), "r"(a[3]), "r"(b[0]), "r"(b[1]));
}

__device__ __forceinline__ void cp16(void* dst_smem, const void* src) {
  uint32_t d = (uint32_t)__cvta_generic_to_shared(dst_smem);
  asm volatile("cp.async.cg.shared.global [%0], [%1], 16;" :: "r"(d), "l"(src));
}

// ---------------- big GEMM (tf32, 2-stage cp.async pipeline) ----------------
// C[M,N] = act(A[M,K] @ W[N,K]^T + bias) (+ residual)
template <int ACT, bool RESID>
__global__ __launch_bounds__(256) void gemm_tf32(
    const float* __restrict__ A, const float* __restrict__ W,
    const float* __restrict__ bias, const float* __restrict__ R,
    float* __restrict__ C, int M, int N, int K) {
  constexpr int BM = 128, BN = 128, BK = 32, S = 36;  // stride 36: conflict-free frags, 144B rows (16B aligned)
  extern __shared__ float sm[];
  float (*As)[BM][S] = reinterpret_cast<float (*)[BM][S]>(sm);
  float (*Bs)[BN][S] = reinterpret_cast<float (*)[BN][S]>(sm + 2 * BM * S);
  const int tid = threadIdx.x;
  const int lane = tid & 31, warp = tid >> 5;
  const int g = lane >> 2, t = lane & 3;
  const int warpM = warp >> 2, warpN = warp & 3;
  const int bm = blockIdx.y * BM, bn = blockIdx.x * BN;
  float c[4][4][4];
#pragma unroll
  for (int i = 0; i < 4; i++)
#pragma unroll
    for (int j = 0; j < 4; j++)
#pragma unroll
      for (int e = 0; e < 4; e++) c[i][j][e] = 0.f;

  auto stage_load = [&](int st, int k0) {
#pragma unroll
    for (int l = 0; l < 4; l++) {
      int idx = (tid + l * 256) * 4;
      int r = idx >> 5, cc = idx & 31;
      cp16(&As[st][r][cc], A + (size_t)(bm + r) * K + k0 + cc);
      cp16(&Bs[st][r][cc], W + (size_t)(bn + r) * K + k0 + cc);
    }
    asm volatile("cp.async.commit_group;");
  };

  const int nk = K / BK;
  stage_load(0, 0);
  for (int kt = 0; kt < nk; kt++) {
    int st = kt & 1;
    if (kt + 1 < nk) {
      stage_load(st ^ 1, (kt + 1) * BK);
      asm volatile("cp.async.wait_group 1;");
    } else {
      asm volatile("cp.async.wait_group 0;");
    }
    __syncthreads();
#pragma unroll
    for (int kk = 0; kk < 4; kk++) {
      const int ks = kk * 8;
      uint32_t a[4][4], bfr[4][2];
#pragma unroll
      for (int i = 0; i < 4; i++) {
        int m0 = warpM * 64 + i * 16;
        a[i][0] = f2tf32(As[st][m0 + g][ks + t]);
        a[i][1] = f2tf32(As[st][m0 + g + 8][ks + t]);
        a[i][2] = f2tf32(As[st][m0 + g][ks + t + 4]);
        a[i][3] = f2tf32(As[st][m0 + g + 8][ks + t + 4]);
      }
#pragma unroll
      for (int j = 0; j < 4; j++) {
        int n0 = warpN * 32 + j * 8;
        bfr[j][0] = f2tf32(Bs[st][n0 + g][ks + t]);
        bfr[j][1] = f2tf32(Bs[st][n0 + g][ks + t + 4]);
      }
#pragma unroll
      for (int i = 0; i < 4; i++)
#pragma unroll
        for (int j = 0; j < 4; j++) mma8(c[i][j], a[i], bfr[j]);
    }
    __syncthreads();
  }

#pragma unroll
  for (int i = 0; i < 4; i++) {
    int r0 = bm + warpM * 64 + i * 16 + g;
#pragma unroll
    for (int j = 0; j < 4; j++) {
      int col = bn + warpN * 32 + j * 8 + 2 * t;
      float b0 = bias[col], b1 = bias[col + 1];
      float v0 = c[i][j][0] + b0, v1 = c[i][j][1] + b1;
      float v2 = c[i][j][2] + b0, v3 = c[i][j][3] + b1;
      if (ACT == 1) {
        v0 = fmaxf(v0, 0.f); v1 = fmaxf(v1, 0.f);
        v2 = fmaxf(v2, 0.f); v3 = fmaxf(v3, 0.f);
      }
      if constexpr (RESID) {
        v0 += R[(size_t)r0 * N + col];
        v1 += R[(size_t)r0 * N + col + 1];
        v2 += R[(size_t)(r0 + 8) * N + col];
        v3 += R[(size_t)(r0 + 8) * N + col + 1];
      }
      *reinterpret_cast<float2*>(C + (size_t)r0 * N + col) = make_float2(v0, v1);
      *reinterpret_cast<float2*>(C + (size_t)(r0 + 8) * N + col) = make_float2(v2, v3);
    }
  }
}

// ---------------- encoder: transpose + position embed + stats partials ----------------
__global__ void enc_pos(const float* __restrict__ inp, const float* __restrict__ Wpos,
                        const float* __restrict__ bpos) {
  __shared__ float tile[32][33];
  int b  = blockIdx.z;
  int c0 = blockIdx.y * 32;
  int t0 = blockIdx.x * 32;
  int tx = threadIdx.x, ty = threadIdx.y;
#pragma unroll
  for (int s = 0; s < 32; s += 8) {
    int cc = ty + s;
    tile[cc][tx] = inp[((size_t)b * kD + (c0 + cc)) * kNT + (t0 + tx)];
  }
  __syncthreads();
  int c = c0 + tx;
  float w0 = Wpos[c * 4 + 0], w1 = Wpos[c * 4 + 1];
  float w2 = Wpos[c * 4 + 2], w3 = Wpos[c * 4 + 3];
  float bp = bpos[c];
  float s1 = 0.f, s2 = 0.f;
#pragma unroll
  for (int s = 0; s < 32; s += 8) {
    int tt = ty + s;
    int tok = t0 + tt;
    float gx = (float)(tok >> 5) * (1.f / 31.f);
    float gy = (float)(tok & 31) * (1.f / 31.f);
    float val = tile[tx][tt] + w0 * gx + w1 * gy + w2 * (1.f - gx) + w3 * (1.f - gy) + bp;
    g_t[((size_t)b * kNT + tok) * kD + c] = val;
    s1 += val;
    s2 += val * val;
  }
  int tid = ty * 32 + tx;
#pragma unroll
  for (int o = 16; o; o >>= 1) {
    s1 += __shfl_xor_sync(0xffffffffu, s1, o);
    s2 += __shfl_xor_sync(0xffffffffu, s2, o);
  }
  __shared__ float r1[8], r2[8];
  if ((tid & 31) == 0) { r1[tid >> 5] = s1; r2[tid >> 5] = s2; }
  __syncthreads();
  if (tid == 0) {
    float a = 0.f, q = 0.f;
#pragma unroll
    for (int i = 0; i < 8; i++) { a += r1[i]; q += r2[i]; }
    int tileIdx = blockIdx.y * 32 + blockIdx.x;
    g_part[(b * 256 + tileIdx) * 2 + 0] = a;
    g_part[(b * 256 + tileIdx) * 2 + 1] = q;
  }
}

__global__ void stats_reduce() {
  int b = blockIdx.x, t = threadIdx.x;
  float s1 = g_part[(b * 256 + t) * 2 + 0];
  float s2 = g_part[(b * 256 + t) * 2 + 1];
#pragma unroll
  for (int o = 16; o; o >>= 1) {
    s1 += __shfl_xor_sync(0xffffffffu, s1, o);
    s2 += __shfl_xor_sync(0xffffffffu, s2, o);
  }
  __shared__ float r1[8], r2[8];
  if ((t & 31) == 0) { r1[t >> 5] = s1; r2[t >> 5] = s2; }
  __syncthreads();
  if (t == 0) {
    float a = 0.f, q = 0.f;
#pragma unroll
    for (int i = 0; i < 8; i++) { a += r1[i]; q += r2[i]; }
    g_stats[b * 2 + 0] = a;
    g_stats[b * 2 + 1] = q;
  }
}

__global__ void ln2_apply(const float* __restrict__ genc, const float* __restrict__ benc) {
  size_t idx = (size_t)blockIdx.x * 256 + threadIdx.x;
  int b  = (int)(idx >> 18);
  int rc = (int)(idx & 262143);
  const float inv = 1.f / 262144.f;
  float m   = g_stats[b * 2 + 0] * inv;
  float var = g_stats[b * 2 + 1] * inv - m * m;
  float r   = rsqrtf(var + kEpsLN);
  g_f[idx] = (g_t[idx] - m) * r * genc[rc] + benc[rc];
}

// ---------------- LayerNorm over last dim (256) ----------------
__global__ void ln_rows(const float* __restrict__ x, float* __restrict__ y,
                        const float* __restrict__ g, const float* __restrict__ bb) {
  int row = blockIdx.x, t = threadIdx.x;
  float v = x[(size_t)row * kD + t];
  float s1 = v, s2 = v * v;
#pragma unroll
  for (int o = 16; o; o >>= 1) {
    s1 += __shfl_xor_sync(0xffffffffu, s1, o);
    s2 += __shfl_xor_sync(0xffffffffu, s2, o);
  }
  __shared__ float w1[8], w2[8];
  if ((t & 31) == 0) { w1[t >> 5] = s1; w2[t >> 5] = s2; }
  __syncthreads();
  float S1 = 0.f, S2 = 0.f;
#pragma unroll
  for (int i = 0; i < 8; i++) { S1 += w1[i]; S2 += w2[i]; }
  float m   = S1 * (1.f / kD);
  float var = S2 * (1.f / kD) - m * m;
  float r   = rsqrtf(var + kEpsLN);
  y[(size_t)row * kD + t] = (v - m) * r * g[t] + bb[t];
}

// ---------------- small SGEMM body (slot-path, fp32) ----------------
template <int BM, int BN, int BK, int TM, int TN, int ACT, bool RESID>
__device__ __forceinline__ void gemm_body(
    const float* __restrict__ A, const float* __restrict__ W,
    const float* __restrict__ bias, const float* __restrict__ R,
    float* __restrict__ C, int M, int N, int K, int bx, int by) {
  __shared__ float As[BK][BM];
  __shared__ float Bs[BK][BN];
  const int tid = threadIdx.x;
  const int bm = by * BM;
  const int bn = bx * BN;
  constexpr int TNN = BN / TN;
  const int tn = tid % TNN;
  const int tm = tid / TNN;
  float acc[TM][TN];
#pragma unroll
  for (int i = 0; i < TM; i++)
#pragma unroll
    for (int j = 0; j < TN; j++) acc[i][j] = 0.f;
  constexpr int LA = (BM * BK) / (256 * 4);
  constexpr int LB = (BN * BK) / (256 * 4);
  for (int k0 = 0; k0 < K; k0 += BK) {
#pragma unroll
    for (int l = 0; l < LA; l++) {
      int fi = (tid + l * 256) * 4;
      int r = fi / BK, c = fi % BK;
      float4 v = *reinterpret_cast<const float4*>(A + (size_t)(bm + r) * K + k0 + c);
      As[c + 0][r] = v.x; As[c + 1][r] = v.y; As[c + 2][r] = v.z; As[c + 3][r] = v.w;
    }
#pragma unroll
    for (int l = 0; l < LB; l++) {
      int fi = (tid + l * 256) * 4;
      int r = fi / BK, c = fi % BK;
      float4 v = *reinterpret_cast<const float4*>(W + (size_t)(bn + r) * K + k0 + c);
      Bs[c + 0][r] = v.x; Bs[c + 1][r] = v.y; Bs[c + 2][r] = v.z; Bs[c + 3][r] = v.w;
    }
    __syncthreads();
#pragma unroll
    for (int kk = 0; kk < BK; kk++) {
      float af[TM], bf[TN];
      float4 a0 = *reinterpret_cast<const float4*>(&As[kk][tm * 4]);
      af[0] = a0.x; af[1] = a0.y; af[2] = a0.z; af[3] = a0.w;
      float4 b0 = *reinterpret_cast<const float4*>(&Bs[kk][tn * 4]);
      bf[0] = b0.x; bf[1] = b0.y; bf[2] = b0.z; bf[3] = b0.w;
#pragma unroll
      for (int i = 0; i < TM; i++)
#pragma unroll
        for (int j = 0; j < TN; j++) acc[i][j] = fmaf(af[i], bf[j], acc[i][j]);
    }
    __syncthreads();
  }
#pragma unroll
  for (int i = 0; i < TM; i++) {
    int r = bm + tm * TM + i;
#pragma unroll
    for (int j = 0; j < TN; j++) {
      int c = bn + tn * TN + j;
      float v = acc[i][j] + bias[c];
      if (ACT == 1) v = fmaxf(v, 0.f);
      if constexpr (RESID) v += R[(size_t)r * N + c];
      C[(size_t)r * N + c] = v;
    }
  }
}

template <int BM, int BN, int BK, int TM, int TN, int ACT, bool RESID>
__global__ __launch_bounds__(256) void gemm_k(
    const float* __restrict__ A, const float* __restrict__ W,
    const float* __restrict__ bias, const float* __restrict__ R,
    float* __restrict__ C, int M, int N, int K) {
  gemm_body<BM, BN, BK, TM, TN, ACT, RESID>(A, W, bias, R, C, M, N, K, blockIdx.x, blockIdx.y);
}

// dual GEMM for GRU: z=0 -> gi = upd@Wih^T, z=1 -> gh = slots@Whh^T
__global__ __launch_bounds__(256) void gemm_gru(
    const float* __restrict__ A0, const float* __restrict__ A1,
    const float* __restrict__ W0, const float* __restrict__ W1,
    const float* __restrict__ b0, const float* __restrict__ b1,
    float* __restrict__ C0, float* __restrict__ C1) {
  const float* A = blockIdx.z ? A1 : A0;
  const float* W = blockIdx.z ? W1 : W0;
  const float* bb = blockIdx.z ? b1 : b0;
  float* C = blockIdx.z ? C1 : C0;
  gemm_body<64, 64, 16, 4, 4, 0, false>(A, W, bb, nullptr, C, kSR, 3 * kD, kD,
                                        blockIdx.x, blockIdx.y);
}

// ---------------- slots init ----------------
__global__ void init_slots(const float* __restrict__ mu, const float* __restrict__ sigma,
                           const float* __restrict__ noise) {
  int idx = blockIdx.x * 256 + threadIdx.x;
  int c = idx & (kD - 1);
  g_slots[idx] = mu[c] + sigma[c] * noise[idx];
}

// ---------------- attention: dots + slot-axis softmax + rowsum partials ----------------
// grid (8 tokBlocks, B), 256 threads. lane = chunk*8 + slot. 2-token ILP.
__global__ void attn_dots() {
  int b = blockIdx.y, yb = blockIdx.x;
  int tid = threadIdx.x, w = tid >> 5, lane = tid & 31;
  int slot = lane & 7, chunk = lane >> 3;
  float4 qf[16];
  const float4* qp = reinterpret_cast<const float4*>(g_q + ((size_t)(b * kNS + slot)) * kD + chunk * 64);
#pragma unroll
  for (int e = 0; e < 16; e++) qf[e] = qp[e];
  float rsacc = 0.f;
  __shared__ float srs[8][kNS];
  for (int jj = 0; jj < 16; jj += 2) {
    int j0 = yb * 128 + w * 16 + jj;
    const float4* kp0 = reinterpret_cast<const float4*>(g_k + ((size_t)(b * kNT + j0)) * kD + chunk * 64);
    const float4* kp1 = reinterpret_cast<const float4*>(g_k + ((size_t)(b * kNT + j0 + 1)) * kD + chunk * 64);
    float pa = 0.f, pb = 0.f;
#pragma unroll
    for (int e = 0; e < 16; e++) {
      float4 k0 = kp0[e], k1 = kp1[e];
      pa += qf[e].x * k0.x + qf[e].y * k0.y + qf[e].z * k0.z + qf[e].w * k0.w;
      pb += qf[e].x * k1.x + qf[e].y * k1.y + qf[e].z * k1.z + qf[e].w * k1.w;
    }
    pa += __shfl_xor_sync(0xffffffffu, pa, 16);
    pb += __shfl_xor_sync(0xffffffffu, pb, 16);
    pa += __shfl_xor_sync(0xffffffffu, pa, 8);
    pb += __shfl_xor_sync(0xffffffffu, pb, 8);
    float da = pa * kScale, db = pb * kScale;
    float ma = da, mb = db;
    ma = fmaxf(ma, __shfl_xor_sync(0xffffffffu, ma, 4));
    mb = fmaxf(mb, __shfl_xor_sync(0xffffffffu, mb, 4));
    ma = fmaxf(ma, __shfl_xor_sync(0xffffffffu, ma, 2));
    mb = fmaxf(mb, __shfl_xor_sync(0xffffffffu, mb, 2));
    ma = fmaxf(ma, __shfl_xor_sync(0xffffffffu, ma, 1));
    mb = fmaxf(mb, __shfl_xor_sync(0xffffffffu, mb, 1));
    float ea = __expf(da - ma), eb = __expf(db - mb);
    float sa = ea, sb = eb;
    sa += __shfl_xor_sync(0xffffffffu, sa, 4);
    sb += __shfl_xor_sync(0xffffffffu, sb, 4);
    sa += __shfl_xor_sync(0xffffffffu, sa, 2);
    sb += __shfl_xor_sync(0xffffffffu, sb, 2);
    sa += __shfl_xor_sync(0xffffffffu, sa, 1);
    sb += __shfl_xor_sync(0xffffffffu, sb, 1);
    float aa = ea / sa + kEpsA;
    float ab = eb / sb + kEpsA;
    if (chunk == 0) {
      g_attn[((size_t)(b * kNT + j0)) * kNS + slot] = aa;
      g_attn[((size_t)(b * kNT + j0 + 1)) * kNS + slot] = ab;
      rsacc += aa + ab;
    }
  }
  if (chunk == 0) srs[w][slot] = rsacc;
  __syncthreads();
  if (tid < kNS) {
    float s = 0.f;
#pragma unroll
    for (int ww = 0; ww < 8; ww++) s += srs[ww][tid];
    g_rsp[(b * 8 + yb) * kNS + tid] = s;
  }
}

// ---------------- attention apply: final upd per batch (fused normalization) ----------------
// grid (B), 512 threads = 2 token-halves x 256 channels
__global__ __launch_bounds__(512) void attn_apply2() {
  int b = blockIdx.x;
  int t = threadIdx.x;
  int half = t >> 8, ch = t & 255;
  __shared__ float sa[2][128][kNS];     // 8 KB attn staging
  __shared__ float part[2][kNS][kD];    // 16 KB partials
  float acc[kNS];
#pragma unroll
  for (int i = 0; i < kNS; i++) acc[i] = 0.f;

  for (int step = 0; step < 4; step++) {
    int tok0 = half * 512 + step * 128;
    const float* ap = g_attn + ((size_t)(b * kNT + tok0)) * kNS;
    float* sl = &sa[half][0][0];
#pragma unroll
    for (int l = 0; l < 4; l++) {
      int id = ch + l * 256;
      sl[id] = ap[id];
    }
    __syncthreads();
    const float* vp = g_v + ((size_t)(b * kNT + tok0)) * kD + ch;
#pragma unroll 8
    for (int j = 0; j < 128; j++) {
      float vt = vp[(size_t)j * kD];
      float4 a0 = *reinterpret_cast<const float4*>(&sa[half][j][0]);
      float4 a1 = *reinterpret_cast<const float4*>(&sa[half][j][4]);
      acc[0] = fmaf(a0.x, vt, acc[0]);
      acc[1] = fmaf(a0.y, vt, acc[1]);
      acc[2] = fmaf(a0.z, vt, acc[2]);
      acc[3] = fmaf(a0.w, vt, acc[3]);
      acc[4] = fmaf(a1.x, vt, acc[4]);
      acc[5] = fmaf(a1.y, vt, acc[5]);
      acc[6] = fmaf(a1.z, vt, acc[6]);
      acc[7] = fmaf(a1.w, vt, acc[7]);
    }
    __syncthreads();
  }
#pragma unroll
  for (int i = 0; i < kNS; i++) part[half][i][ch] = acc[i];
  __syncthreads();
  if (half == 0) {
#pragma unroll
    for (int i = 0; i < kNS; i++) {
      float rs = 0.f;
#pragma unroll
      for (int yb = 0; yb < 8; yb++) rs += g_rsp[(b * 8 + yb) * kNS + i];
      g_upd[((size_t)(b * kNS + i)) * kD + ch] = (part[0][i][ch] + part[1][i][ch]) / rs;
    }
  }
}

// ---------------- GRU gates + fused LayerNorm ----------------
__global__ void gru_ln(const float* __restrict__ gff, const float* __restrict__ bffv) {
  int row = blockIdx.x, c = threadIdx.x;
  size_t base = (size_t)row * 3 * kD + c;
  float ir = g_gi[base], iz = g_gi[base + kD], in_ = g_gi[base + 2 * kD];
  float hr = g_gh[base], hz = g_gh[base + kD], hn = g_gh[base + 2 * kD];
  float r = 1.f / (1.f + __expf(-(ir + hr)));
  float z = 1.f / (1.f + __expf(-(iz + hz)));
  float n = tanhf(in_ + r * hn);
  float h = g_slots[(size_t)row * kD + c];
  float v = (1.f - z) * n + z * h;
  g_ns[(size_t)row * kD + c] = v;
  float s1 = v, s2 = v * v;
#pragma unroll
  for (int o = 16; o; o >>= 1) {
    s1 += __shfl_xor_sync(0xffffffffu, s1, o);
    s2 += __shfl_xor_sync(0xffffffffu, s2, o);
  }
  __shared__ float w1[8], w2[8];
  if ((c & 31) == 0) { w1[c >> 5] = s1; w2[c >> 5] = s2; }
  __syncthreads();
  float S1 = 0.f, S2 = 0.f;
#pragma unroll
  for (int i = 0; i < 8; i++) { S1 += w1[i]; S2 += w2[i]; }
  float m   = S1 * (1.f / kD);
  float var = S2 * (1.f / kD) - m * m;
  float rr  = rsqrtf(var + kEpsLN);
  g_lnns[(size_t)row * kD + c] = (v - m) * rr * gff[c] + bffv[c];
}

// ---------------- launch ----------------
extern "C" void kernel_launch(void* const* d_in, const int* in_sizes, int n_in,
                              void* d_out, int out_size) {
  const float* inp   = (const float*)d_in[0];
  const float* noise = (const float*)d_in[1];
  const float* Wpos  = (const float*)d_in[2];
  const float* bpos  = (const float*)d_in[3];
  const float* genc  = (const float*)d_in[4];
  const float* benc  = (const float*)d_in[5];
  const float* Wm1   = (const float*)d_in[6];
  const float* bm1   = (const float*)d_in[7];
  const float* Wm2   = (const float*)d_in[8];
  const float* bm2   = (const float*)d_in[9];
  const float* gin   = (const float*)d_in[10];
  const float* bin   = (const float*)d_in[11];
  const float* Wq    = (const float*)d_in[12];
  const float* bq    = (const float*)d_in[13];
  const float* Wk    = (const float*)d_in[14];
  const float* bk    = (const float*)d_in[15];
  const float* Wv    = (const float*)d_in[16];
  const float* bv    = (const float*)d_in[17];
  const float* Wih   = (const float*)d_in[18];
  const float* Whh   = (const float*)d_in[19];
  const float* bih   = (const float*)d_in[20];
  const float* bhh   = (const float*)d_in[21];
  const float* gs    = (const float*)d_in[22];
  const float* bs    = (const float*)d_in[23];
  const float* gff   = (const float*)d_in[24];
  const float* bff   = (const float*)d_in[25];
  const float* Wf1   = (const float*)d_in[26];
  const float* bf1   = (const float*)d_in[27];
  const float* Wf2   = (const float*)d_in[28];
  const float* bf2   = (const float*)d_in[29];
  const float* mu    = (const float*)d_in[30];
  const float* sigma = (const float*)d_in[31];
  float* out = (float*)d_out;

  float *pt, *pf, *pk, *pv, *pslots, *psln, *pq, *pupd, *pgi, *pgh, *pns, *plnns, *ph;
  cudaGetSymbolAddress((void**)&pt, g_t);
  cudaGetSymbolAddress((void**)&pf, g_f);
  cudaGetSymbolAddress((void**)&pk, g_k);
  cudaGetSymbolAddress((void**)&pv, g_v);
  cudaGetSymbolAddress((void**)&pslots, g_slots);
  cudaGetSymbolAddress((void**)&psln, g_sln);
  cudaGetSymbolAddress((void**)&pq, g_q);
  cudaGetSymbolAddress((void**)&pupd, g_upd);
  cudaGetSymbolAddress((void**)&pgi, g_gi);
  cudaGetSymbolAddress((void**)&pgh, g_gh);
  cudaGetSymbolAddress((void**)&pns, g_ns);
  cudaGetSymbolAddress((void**)&plnns, g_lnns);
  cudaGetSymbolAddress((void**)&ph, g_h);

  constexpr int kGemmSmem = 2 * 2 * 128 * 36 * 4;  // 73728 B
  static bool attr_done = false;
  if (!attr_done) {
    cudaFuncSetAttribute(gemm_tf32<1, false>, cudaFuncAttributeMaxDynamicSharedMemorySize, kGemmSmem);
    cudaFuncSetAttribute(gemm_tf32<0, false>, cudaFuncAttributeMaxDynamicSharedMemorySize, kGemmSmem);
    attr_done = true;
  }

  // ---- encoder ----
  enc_pos<<<dim3(32, 8, kB), dim3(32, 8)>>>(inp, Wpos, bpos);
  stats_reduce<<<kB, 256>>>();
  ln2_apply<<<kRows, 256>>>(genc, benc);
  gemm_tf32<1, false><<<dim3(2, 512), 256, kGemmSmem>>>(pf, Wm1, bm1, nullptr, pt, kRows, kD, kD);
  gemm_tf32<1, false><<<dim3(2, 512), 256, kGemmSmem>>>(pt, Wm2, bm2, nullptr, pf, kRows, kD, kD);
  ln_rows<<<kRows, 256>>>(pf, pt, gin, bin);
  gemm_tf32<0, false><<<dim3(2, 512), 256, kGemmSmem>>>(pt, Wk, bk, nullptr, pk, kRows, kD, kD);
  gemm_tf32<0, false><<<dim3(2, 512), 256, kGemmSmem>>>(pt, Wv, bv, nullptr, pv, kRows, kD, kD);

  // ---- slots ----
  init_slots<<<kSR, 256>>>(mu, sigma, noise);

  for (int it = 0; it < 6; ++it) {
    ln_rows<<<kSR, 256>>>(pslots, psln, gs, bs);
    gemm_k<64, 64, 16, 4, 4, 0, false><<<dim3(4, 8), 256>>>(psln, Wq, bq, nullptr, pq, kSR, kD, kD);
    attn_dots<<<dim3(8, kB), 256>>>();
    attn_apply2<<<kB, 512>>>();
    gemm_gru<<<dim3(12, 8, 2), 256>>>(pupd, pslots, Wih, Whh, bih, bhh, pgi, pgh);
    gru_ln<<<kSR, 256>>>(gff, bff);
    gemm_k<64, 64, 16, 4, 4, 1, false><<<dim3(4, 8), 256>>>(plnns, Wf1, bf1, nullptr, ph, kSR, kD, kD);
    float* dst = (it == 5) ? out : pslots;
    gemm_k<64, 64, 16, 4, 4, 0, true><<<dim3(4, 8), 256>>>(ph, Wf2, bf2, pns, dst, kSR, kD, kD);
  }
}

// round 17
// speedup vs baseline: 1.2845x; 1.2845x over previous
#include <cuda_runtime.h>
#include <cstdint>

// ---------------- problem constants ----------------
namespace {
constexpr int kB   = 64;
constexpr int kD   = 256;
constexpr int kNS  = 8;
constexpr int kNT  = 1024;            // RES*RES
constexpr int kRows = kB * kNT;       // 65536 encoder rows
constexpr int kSR   = kB * kNS;       // 512 slot rows
constexpr float kScale = 0.0625f;     // 256^-0.5
constexpr float kEpsA  = 1e-8f;
constexpr float kEpsLN = 1e-5f;
}

// ---------------- scratch (device globals; no allocation) ----------------
__device__ float g_t[kRows * kD];
__device__ float g_f[kRows * kD];
__device__ float g_k[kRows * kD];
__device__ float g_v[kRows * kD];
__device__ float g_part[kB * 256 * 2];
__device__ float g_stats[kB * 2];
__device__ float g_slots[kSR * kD];
__device__ float g_sln[kSR * kD];
__device__ float g_q[kSR * kD];
__device__ float g_rsp[kB * 8 * kNS];        // rowsum partials per chunk
__device__ float g_updp[kB * 8 * kNS * kD];  // upd partials per chunk (4 MB)
__device__ float g_upd[kSR * kD];
__device__ float g_gi[kSR * 3 * kD];
__device__ float g_gh[kSR * 3 * kD];
__device__ float g_ns[kSR * kD];
__device__ float g_lnns[kSR * kD];
__device__ float g_h[kSR * kD];

// ---------------- mma helpers ----------------
__device__ __forceinline__ void mma8(float* c, const uint32_t* a, const uint32_t* b) {
  asm volatile(
      "mma.sync.aligned.m16n8k8.row.col.f32.tf32.tf32.f32 "
      "{%0,%1,%2,%3}, {%4,%5,%6,%7}, {%8,%9}, {%0,%1,%2,%3};\n"
      : "+f"(c[0]), "+f"(c[1]), "+f"(c[2]), "+f"(c[3])
      : "r"(a[0]), "r"(a[1]), "r"(a[2]), "r"(a[3]), "r"(b[0]), "r"(b[1]));
}

__device__ __forceinline__ void cp16(void* dst_smem, const void* src) {
  uint32_t d = (uint32_t)__cvta_generic_to_shared(dst_smem);
  asm volatile("cp.async.cg.shared.global [%0], [%1], 16;" :: "r"(d), "l"(src));
}

// ---------------- big GEMM (tf32, 2-stage cp.async pipeline) ----------------
// C[M,N] = act(A[M,K] @ W[N,K]^T + bias)
template <int ACT>
__global__ __launch_bounds__(256, 2) void gemm_tf32(
    const float* __restrict__ A, const float* __restrict__ W,
    const float* __restrict__ bias,
    float* __restrict__ C, int M, int N, int K) {
  constexpr int BM = 128, BN = 128, BK = 32, S = 36;
  extern __shared__ float sm[];
  float (*As)[BM][S] = reinterpret_cast<float (*)[BM][S]>(sm);
  float (*Bs)[BN][S] = reinterpret_cast<float (*)[BN][S]>(sm + 2 * BM * S);
  const int tid = threadIdx.x;
  const int lane = tid & 31, warp = tid >> 5;
  const int g = lane >> 2, t = lane & 3;
  const int warpM = warp >> 2, warpN = warp & 3;
  const int bm = blockIdx.y * BM, bn = blockIdx.x * BN;
  float c[4][4][4];
#pragma unroll
  for (int i = 0; i < 4; i++)
#pragma unroll
    for (int j = 0; j < 4; j++)
#pragma unroll
      for (int e = 0; e < 4; e++) c[i][j][e] = 0.f;

  auto stage_load = [&](int st, int k0) {
#pragma unroll
    for (int l = 0; l < 4; l++) {
      int idx = (tid + l * 256) * 4;
      int r = idx >> 5, cc = idx & 31;
      cp16(&As[st][r][cc], A + (size_t)(bm + r) * K + k0 + cc);
      cp16(&Bs[st][r][cc], W + (size_t)(bn + r) * K + k0 + cc);
    }
    asm volatile("cp.async.commit_group;");
  };

  const int nk = K / BK;
  stage_load(0, 0);
  for (int kt = 0; kt < nk; kt++) {
    int st = kt & 1;
    if (kt + 1 < nk) {
      stage_load(st ^ 1, (kt + 1) * BK);
      asm volatile("cp.async.wait_group 1;");
    } else {
      asm volatile("cp.async.wait_group 0;");
    }
    __syncthreads();
#pragma unroll
    for (int kk = 0; kk < 4; kk++) {
      const int ks = kk * 8;
      uint32_t a[4][4], bfr[4][2];
#pragma unroll
      for (int i = 0; i < 4; i++) {
        int m0 = warpM * 64 + i * 16;
        a[i][0] = __float_as_uint(As[st][m0 + g][ks + t]);
        a[i][1] = __float_as_uint(As[st][m0 + g + 8][ks + t]);
        a[i][2] = __float_as_uint(As[st][m0 + g][ks + t + 4]);
        a[i][3] = __float_as_uint(As[st][m0 + g + 8][ks + t + 4]);
      }
#pragma unroll
      for (int j = 0; j < 4; j++) {
        int n0 = warpN * 32 + j * 8;
        bfr[j][0] = __float_as_uint(Bs[st][n0 + g][ks + t]);
        bfr[j][1] = __float_as_uint(Bs[st][n0 + g][ks + t + 4]);
      }
#pragma unroll
      for (int i = 0; i < 4; i++)
#pragma unroll
        for (int j = 0; j < 4; j++) mma8(c[i][j], a[i], bfr[j]);
    }
    __syncthreads();
  }

#pragma unroll
  for (int i = 0; i < 4; i++) {
    int r0 = bm + warpM * 64 + i * 16 + g;
#pragma unroll
    for (int j = 0; j < 4; j++) {
      int col = bn + warpN * 32 + j * 8 + 2 * t;
      float b0 = bias[col], b1 = bias[col + 1];
      float v0 = c[i][j][0] + b0, v1 = c[i][j][1] + b1;
      float v2 = c[i][j][2] + b0, v3 = c[i][j][3] + b1;
      if (ACT == 1) {
        v0 = fmaxf(v0, 0.f); v1 = fmaxf(v1, 0.f);
        v2 = fmaxf(v2, 0.f); v3 = fmaxf(v3, 0.f);
      }
      *reinterpret_cast<float2*>(C + (size_t)r0 * N + col) = make_float2(v0, v1);
      *reinterpret_cast<float2*>(C + (size_t)(r0 + 8) * N + col) = make_float2(v2, v3);
    }
  }
}

// ---------------- encoder: transpose + position embed + stats partials ----------------
__global__ void enc_pos(const float* __restrict__ inp, const float* __restrict__ Wpos,
                        const float* __restrict__ bpos) {
  __shared__ float tile[32][33];
  int b  = blockIdx.z;
  int c0 = blockIdx.y * 32;
  int t0 = blockIdx.x * 32;
  int tx = threadIdx.x, ty = threadIdx.y;
#pragma unroll
  for (int s = 0; s < 32; s += 8) {
    int cc = ty + s;
    tile[cc][tx] = inp[((size_t)b * kD + (c0 + cc)) * kNT + (t0 + tx)];
  }
  __syncthreads();
  int c = c0 + tx;
  float w0 = Wpos[c * 4 + 0], w1 = Wpos[c * 4 + 1];
  float w2 = Wpos[c * 4 + 2], w3 = Wpos[c * 4 + 3];
  float bp = bpos[c];
  float s1 = 0.f, s2 = 0.f;
#pragma unroll
  for (int s = 0; s < 32; s += 8) {
    int tt = ty + s;
    int tok = t0 + tt;
    float gx = (float)(tok >> 5) * (1.f / 31.f);
    float gy = (float)(tok & 31) * (1.f / 31.f);
    float val = tile[tx][tt] + w0 * gx + w1 * gy + w2 * (1.f - gx) + w3 * (1.f - gy) + bp;
    g_t[((size_t)b * kNT + tok) * kD + c] = val;
    s1 += val;
    s2 += val * val;
  }
  int tid = ty * 32 + tx;
#pragma unroll
  for (int o = 16; o; o >>= 1) {
    s1 += __shfl_xor_sync(0xffffffffu, s1, o);
    s2 += __shfl_xor_sync(0xffffffffu, s2, o);
  }
  __shared__ float r1[8], r2[8];
  if ((tid & 31) == 0) { r1[tid >> 5] = s1; r2[tid >> 5] = s2; }
  __syncthreads();
  if (tid == 0) {
    float a = 0.f, q = 0.f;
#pragma unroll
    for (int i = 0; i < 8; i++) { a += r1[i]; q += r2[i]; }
    int tileIdx = blockIdx.y * 32 + blockIdx.x;
    g_part[(b * 256 + tileIdx) * 2 + 0] = a;
    g_part[(b * 256 + tileIdx) * 2 + 1] = q;
  }
}

__global__ void stats_reduce() {
  int b = blockIdx.x, t = threadIdx.x;
  float s1 = g_part[(b * 256 + t) * 2 + 0];
  float s2 = g_part[(b * 256 + t) * 2 + 1];
#pragma unroll
  for (int o = 16; o; o >>= 1) {
    s1 += __shfl_xor_sync(0xffffffffu, s1, o);
    s2 += __shfl_xor_sync(0xffffffffu, s2, o);
  }
  __shared__ float r1[8], r2[8];
  if ((t & 31) == 0) { r1[t >> 5] = s1; r2[t >> 5] = s2; }
  __syncthreads();
  if (t == 0) {
    float a = 0.f, q = 0.f;
#pragma unroll
    for (int i = 0; i < 8; i++) { a += r1[i]; q += r2[i]; }
    g_stats[b * 2 + 0] = a;
    g_stats[b * 2 + 1] = q;
  }
}

__global__ void ln2_apply(const float* __restrict__ genc, const float* __restrict__ benc) {
  size_t idx = (size_t)blockIdx.x * 256 + threadIdx.x;
  int b  = (int)(idx >> 18);
  int rc = (int)(idx & 262143);
  const float inv = 1.f / 262144.f;
  float m   = g_stats[b * 2 + 0] * inv;
  float var = g_stats[b * 2 + 1] * inv - m * m;
  float r   = rsqrtf(var + kEpsLN);
  g_f[idx] = (g_t[idx] - m) * r * genc[rc] + benc[rc];
}

// ---------------- LayerNorm over last dim (256) ----------------
__global__ void ln_rows(const float* __restrict__ x, float* __restrict__ y,
                        const float* __restrict__ g, const float* __restrict__ bb) {
  int row = blockIdx.x, t = threadIdx.x;
  float v = x[(size_t)row * kD + t];
  float s1 = v, s2 = v * v;
#pragma unroll
  for (int o = 16; o; o >>= 1) {
    s1 += __shfl_xor_sync(0xffffffffu, s1, o);
    s2 += __shfl_xor_sync(0xffffffffu, s2, o);
  }
  __shared__ float w1[8], w2[8];
  if ((t & 31) == 0) { w1[t >> 5] = s1; w2[t >> 5] = s2; }
  __syncthreads();
  float S1 = 0.f, S2 = 0.f;
#pragma unroll
  for (int i = 0; i < 8; i++) { S1 += w1[i]; S2 += w2[i]; }
  float m   = S1 * (1.f / kD);
  float var = S2 * (1.f / kD) - m * m;
  float r   = rsqrtf(var + kEpsLN);
  y[(size_t)row * kD + t] = (v - m) * r * g[t] + bb[t];
}

// ---------------- small SGEMM body (slot-path, fp32) ----------------
template <int BM, int BN, int BK, int TM, int TN, int ACT, bool RESID>
__device__ __forceinline__ void gemm_body(
    const float* __restrict__ A, const float* __restrict__ W,
    const float* __restrict__ bias, const float* __restrict__ R,
    float* __restrict__ C, int M, int N, int K, int bx, int by) {
  __shared__ float As[BK][BM];
  __shared__ float Bs[BK][BN];
  const int tid = threadIdx.x;
  const int bm = by * BM;
  const int bn = bx * BN;
  constexpr int TNN = BN / TN;
  const int tn = tid % TNN;
  const int tm = tid / TNN;
  float acc[TM][TN];
#pragma unroll
  for (int i = 0; i < TM; i++)
#pragma unroll
    for (int j = 0; j < TN; j++) acc[i][j] = 0.f;
  constexpr int LA = (BM * BK) / (256 * 4);
  constexpr int LB = (BN * BK) / (256 * 4);
  for (int k0 = 0; k0 < K; k0 += BK) {
#pragma unroll
    for (int l = 0; l < LA; l++) {
      int fi = (tid + l * 256) * 4;
      int r = fi / BK, c = fi % BK;
      float4 v = *reinterpret_cast<const float4*>(A + (size_t)(bm + r) * K + k0 + c);
      As[c + 0][r] = v.x; As[c + 1][r] = v.y; As[c + 2][r] = v.z; As[c + 3][r] = v.w;
    }
#pragma unroll
    for (int l = 0; l < LB; l++) {
      int fi = (tid + l * 256) * 4;
      int r = fi / BK, c = fi % BK;
      float4 v = *reinterpret_cast<const float4*>(W + (size_t)(bn + r) * K + k0 + c);
      Bs[c + 0][r] = v.x; Bs[c + 1][r] = v.y; Bs[c + 2][r] = v.z; Bs[c + 3][r] = v.w;
    }
    __syncthreads();
#pragma unroll
    for (int kk = 0; kk < BK; kk++) {
      float af[TM], bf[TN];
      float4 a0 = *reinterpret_cast<const float4*>(&As[kk][tm * 4]);
      af[0] = a0.x; af[1] = a0.y; af[2] = a0.z; af[3] = a0.w;
      float4 b0 = *reinterpret_cast<const float4*>(&Bs[kk][tn * 4]);
      bf[0] = b0.x; bf[1] = b0.y; bf[2] = b0.z; bf[3] = b0.w;
#pragma unroll
      for (int i = 0; i < TM; i++)
#pragma unroll
        for (int j = 0; j < TN; j++) acc[i][j] = fmaf(af[i], bf[j], acc[i][j]);
    }
    __syncthreads();
  }
#pragma unroll
  for (int i = 0; i < TM; i++) {
    int r = bm + tm * TM + i;
#pragma unroll
    for (int j = 0; j < TN; j++) {
      int c = bn + tn * TN + j;
      float v = acc[i][j] + bias[c];
      if (ACT == 1) v = fmaxf(v, 0.f);
      if constexpr (RESID) v += R[(size_t)r * N + c];
      C[(size_t)r * N + c] = v;
    }
  }
}

template <int BM, int BN, int BK, int TM, int TN, int ACT, bool RESID>
__global__ __launch_bounds__(256) void gemm_k(
    const float* __restrict__ A, const float* __restrict__ W,
    const float* __restrict__ bias, const float* __restrict__ R,
    float* __restrict__ C, int M, int N, int K) {
  gemm_body<BM, BN, BK, TM, TN, ACT, RESID>(A, W, bias, R, C, M, N, K, blockIdx.x, blockIdx.y);
}

// dual GEMM for GRU gates
__global__ __launch_bounds__(256) void gemm_gru(
    const float* __restrict__ A0, const float* __restrict__ A1,
    const float* __restrict__ W0, const float* __restrict__ W1,
    const float* __restrict__ b0, const float* __restrict__ b1,
    float* __restrict__ C0, float* __restrict__ C1) {
  const float* A = blockIdx.z ? A1 : A0;
  const float* W = blockIdx.z ? W1 : W0;
  const float* bb = blockIdx.z ? b1 : b0;
  float* C = blockIdx.z ? C1 : C0;
  gemm_body<64, 64, 16, 4, 4, 0, false>(A, W, bb, nullptr, C, kSR, 3 * kD, kD,
                                        blockIdx.x, blockIdx.y);
}

// ---------------- slots init ----------------
__global__ void init_slots(const float* __restrict__ mu, const float* __restrict__ sigma,
                           const float* __restrict__ noise) {
  int idx = blockIdx.x * 256 + threadIdx.x;
  int c = idx & (kD - 1);
  g_slots[idx] = mu[c] + sigma[c] * noise[idx];
}

// ---------------- fused attention: dots + softmax + apply over one 128-token chunk ----------------
// grid (8 chunks, B), 256 threads.
__global__ __launch_bounds__(256) void attn_fused() {
  int b = blockIdx.y, yb = blockIdx.x;
  int tid = threadIdx.x, w = tid >> 5, lane = tid & 31;
  int slot = lane & 7, chunk = lane >> 3;
  __shared__ float sa[128][kNS];   // attn for this chunk, token-major
  __shared__ float srs[8][kNS];    // per-warp rowsum partials

  // ---- phase A: dots + slot softmax (warp w handles tokens w*16..w*16+15) ----
  float4 qf[16];
  const float4* qp = reinterpret_cast<const float4*>(g_q + ((size_t)(b * kNS + slot)) * kD + chunk * 64);
#pragma unroll
  for (int e = 0; e < 16; e++) qf[e] = qp[e];
  float rsacc = 0.f;
  for (int jj = 0; jj < 16; jj += 2) {
    int jt = w * 16 + jj;
    int j0 = yb * 128 + jt;
    const float4* kp0 = reinterpret_cast<const float4*>(g_k + ((size_t)(b * kNT + j0)) * kD + chunk * 64);
    const float4* kp1 = reinterpret_cast<const float4*>(g_k + ((size_t)(b * kNT + j0 + 1)) * kD + chunk * 64);
    float pa = 0.f, pb = 0.f;
#pragma unroll
    for (int e = 0; e < 16; e++) {
      float4 k0 = kp0[e], k1 = kp1[e];
      pa += qf[e].x * k0.x + qf[e].y * k0.y + qf[e].z * k0.z + qf[e].w * k0.w;
      pb += qf[e].x * k1.x + qf[e].y * k1.y + qf[e].z * k1.z + qf[e].w * k1.w;
    }
    pa += __shfl_xor_sync(0xffffffffu, pa, 16);
    pb += __shfl_xor_sync(0xffffffffu, pb, 16);
    pa += __shfl_xor_sync(0xffffffffu, pa, 8);
    pb += __shfl_xor_sync(0xffffffffu, pb, 8);
    float da = pa * kScale, db = pb * kScale;
    float ma = da, mb = db;
    ma = fmaxf(ma, __shfl_xor_sync(0xffffffffu, ma, 4));
    mb = fmaxf(mb, __shfl_xor_sync(0xffffffffu, mb, 4));
    ma = fmaxf(ma, __shfl_xor_sync(0xffffffffu, ma, 2));
    mb = fmaxf(mb, __shfl_xor_sync(0xffffffffu, mb, 2));
    ma = fmaxf(ma, __shfl_xor_sync(0xffffffffu, ma, 1));
    mb = fmaxf(mb, __shfl_xor_sync(0xffffffffu, mb, 1));
    float ea = __expf(da - ma), eb = __expf(db - mb);
    float sa1 = ea, sb1 = eb;
    sa1 += __shfl_xor_sync(0xffffffffu, sa1, 4);
    sb1 += __shfl_xor_sync(0xffffffffu, sb1, 4);
    sa1 += __shfl_xor_sync(0xffffffffu, sa1, 2);
    sb1 += __shfl_xor_sync(0xffffffffu, sb1, 2);
    sa1 += __shfl_xor_sync(0xffffffffu, sa1, 1);
    sb1 += __shfl_xor_sync(0xffffffffu, sb1, 1);
    float aa = ea / sa1 + kEpsA;
    float ab = eb / sb1 + kEpsA;
    if (chunk == 0) {
      sa[jt][slot] = aa;
      sa[jt + 1][slot] = ab;
      rsacc += aa + ab;
    }
  }
  if (chunk == 0) srs[w][slot] = rsacc;
  __syncthreads();
  if (tid < kNS) {
    float s = 0.f;
#pragma unroll
    for (int ww = 0; ww < 8; ww++) s += srs[ww][tid];
    g_rsp[(b * 8 + yb) * kNS + tid] = s;
  }

  // ---- phase B: upd partial = attn_chunk^T @ v_chunk (thread = channel) ----
  float acc[kNS];
#pragma unroll
  for (int i = 0; i < kNS; i++) acc[i] = 0.f;
  const float* vp = g_v + ((size_t)(b * kNT + yb * 128)) * kD + tid;
#pragma unroll 8
  for (int j = 0; j < 128; j++) {
    float vt = vp[(size_t)j * kD];
    float4 a0 = *reinterpret_cast<const float4*>(&sa[j][0]);
    float4 a1 = *reinterpret_cast<const float4*>(&sa[j][4]);
    acc[0] = fmaf(a0.x, vt, acc[0]);
    acc[1] = fmaf(a0.y, vt, acc[1]);
    acc[2] = fmaf(a0.z, vt, acc[2]);
    acc[3] = fmaf(a0.w, vt, acc[3]);
    acc[4] = fmaf(a1.x, vt, acc[4]);
    acc[5] = fmaf(a1.y, vt, acc[5]);
    acc[6] = fmaf(a1.z, vt, acc[6]);
    acc[7] = fmaf(a1.w, vt, acc[7]);
  }
#pragma unroll
  for (int i = 0; i < kNS; i++)
    g_updp[(((size_t)(b * 8 + yb)) * kNS + i) * kD + tid] = acc[i];
}

// grid (B*NS), 256 threads: combine 8 chunk partials + normalization
__global__ void upd_reduce() {
  int bi = blockIdx.x;
  int b = bi / kNS, i = bi % kNS;
  int t = threadIdx.x;
  float rs = 0.f;
#pragma unroll
  for (int yb = 0; yb < 8; yb++) rs += g_rsp[(b * 8 + yb) * kNS + i];
  float s = 0.f;
#pragma unroll
  for (int yb = 0; yb < 8; yb++)
    s += g_updp[(((size_t)(b * 8 + yb)) * kNS + i) * kD + t];
  g_upd[(size_t)bi * kD + t] = s / rs;
}

// ---------------- GRU gates + fused LayerNorm ----------------
__global__ void gru_ln(const float* __restrict__ gff, const float* __restrict__ bffv) {
  int row = blockIdx.x, c = threadIdx.x;
  size_t base = (size_t)row * 3 * kD + c;
  float ir = g_gi[base], iz = g_gi[base + kD], in_ = g_gi[base + 2 * kD];
  float hr = g_gh[base], hz = g_gh[base + kD], hn = g_gh[base + 2 * kD];
  float r = 1.f / (1.f + __expf(-(ir + hr)));
  float z = 1.f / (1.f + __expf(-(iz + hz)));
  float n = tanhf(in_ + r * hn);
  float h = g_slots[(size_t)row * kD + c];
  float v = (1.f - z) * n + z * h;
  g_ns[(size_t)row * kD + c] = v;
  float s1 = v, s2 = v * v;
#pragma unroll
  for (int o = 16; o; o >>= 1) {
    s1 += __shfl_xor_sync(0xffffffffu, s1, o);
    s2 += __shfl_xor_sync(0xffffffffu, s2, o);
  }
  __shared__ float w1[8], w2[8];
  if ((c & 31) == 0) { w1[c >> 5] = s1; w2[c >> 5] = s2; }
  __syncthreads();
  float S1 = 0.f, S2 = 0.f;
#pragma unroll
  for (int i = 0; i < 8; i++) { S1 += w1[i]; S2 += w2[i]; }
  float m   = S1 * (1.f / kD);
  float var = S2 * (1.f / kD) - m * m;
  float rr  = rsqrtf(var + kEpsLN);
  g_lnns[(size_t)row * kD + c] = (v - m) * rr * gff[c] + bffv[c];
}

// ---------------- launch ----------------
extern "C" void kernel_launch(void* const* d_in, const int* in_sizes, int n_in,
                              void* d_out, int out_size) {
  const float* inp   = (const float*)d_in[0];
  const float* noise = (const float*)d_in[1];
  const float* Wpos  = (const float*)d_in[2];
  const float* bpos  = (const float*)d_in[3];
  const float* genc  = (const float*)d_in[4];
  const float* benc  = (const float*)d_in[5];
  const float* Wm1   = (const float*)d_in[6];
  const float* bm1   = (const float*)d_in[7];
  const float* Wm2   = (const float*)d_in[8];
  const float* bm2   = (const float*)d_in[9];
  const float* gin   = (const float*)d_in[10];
  const float* bin   = (const float*)d_in[11];
  const float* Wq    = (const float*)d_in[12];
  const float* bq    = (const float*)d_in[13];
  const float* Wk    = (const float*)d_in[14];
  const float* bk    = (const float*)d_in[15];
  const float* Wv    = (const float*)d_in[16];
  const float* bv    = (const float*)d_in[17];
  const float* Wih   = (const float*)d_in[18];
  const float* Whh   = (const float*)d_in[19];
  const float* bih   = (const float*)d_in[20];
  const float* bhh   = (const float*)d_in[21];
  const float* gs    = (const float*)d_in[22];
  const float* bs    = (const float*)d_in[23];
  const float* gff   = (const float*)d_in[24];
  const float* bff   = (const float*)d_in[25];
  const float* Wf1   = (const float*)d_in[26];
  const float* bf1   = (const float*)d_in[27];
  const float* Wf2   = (const float*)d_in[28];
  const float* bf2   = (const float*)d_in[29];
  const float* mu    = (const float*)d_in[30];
  const float* sigma = (const float*)d_in[31];
  float* out = (float*)d_out;

  float *pt, *pf, *pk, *pv, *pslots, *psln, *pq, *pupd, *pgi, *pgh, *pns, *plnns, *ph;
  cudaGetSymbolAddress((void**)&pt, g_t);
  cudaGetSymbolAddress((void**)&pf, g_f);
  cudaGetSymbolAddress((void**)&pk, g_k);
  cudaGetSymbolAddress((void**)&pv, g_v);
  cudaGetSymbolAddress((void**)&pslots, g_slots);
  cudaGetSymbolAddress((void**)&psln, g_sln);
  cudaGetSymbolAddress((void**)&pq, g_q);
  cudaGetSymbolAddress((void**)&pupd, g_upd);
  cudaGetSymbolAddress((void**)&pgi, g_gi);
  cudaGetSymbolAddress((void**)&pgh, g_gh);
  cudaGetSymbolAddress((void**)&pns, g_ns);
  cudaGetSymbolAddress((void**)&plnns, g_lnns);
  cudaGetSymbolAddress((void**)&ph, g_h);

  constexpr int kGemmSmem = 2 * 2 * 128 * 36 * 4;  // 73728 B
  cudaFuncSetAttribute(gemm_tf32<1>, cudaFuncAttributeMaxDynamicSharedMemorySize, kGemmSmem);
  cudaFuncSetAttribute(gemm_tf32<0>, cudaFuncAttributeMaxDynamicSharedMemorySize, kGemmSmem);

  // ---- encoder ----
  enc_pos<<<dim3(32, 8, kB), dim3(32, 8)>>>(inp, Wpos, bpos);
  stats_reduce<<<kB, 256>>>();
  ln2_apply<<<kRows, 256>>>(genc, benc);
  gemm_tf32<1><<<dim3(2, 512), 256, kGemmSmem>>>(pf, Wm1, bm1, pt, kRows, kD, kD);
  gemm_tf32<1><<<dim3(2, 512), 256, kGemmSmem>>>(pt, Wm2, bm2, pf, kRows, kD, kD);
  ln_rows<<<kRows, 256>>>(pf, pt, gin, bin);
  gemm_tf32<0><<<dim3(2, 512), 256, kGemmSmem>>>(pt, Wk, bk, pk, kRows, kD, kD);
  gemm_tf32<0><<<dim3(2, 512), 256, kGemmSmem>>>(pt, Wv, bv, pv, kRows, kD, kD);

  // ---- slots ----
  init_slots<<<kSR, 256>>>(mu, sigma, noise);

  for (int it = 0; it < 6; ++it) {
    ln_rows<<<kSR, 256>>>(pslots, psln, gs, bs);
    gemm_k<64, 64, 16, 4, 4, 0, false><<<dim3(4, 8), 256>>>(psln, Wq, bq, nullptr, pq, kSR, kD, kD);
    attn_fused<<<dim3(8, kB), 256>>>();
    upd_reduce<<<kSR, 256>>>();
    gemm_gru<<<dim3(12, 8, 2), 256>>>(pupd, pslots, Wih, Whh, bih, bhh, pgi, pgh);
    gru_ln<<<kSR, 256>>>(gff, bff);
    gemm_k<64, 64, 16, 4, 4, 1, false><<<dim3(4, 8), 256>>>(plnns, Wf1, bf1, nullptr, ph, kSR, kD, kD);
    float* dst = (it == 5) ? out : pslots;
    gemm_k<64, 64, 16, 4, 4, 0, true><<<dim3(4, 8), 256>>>(ph, Wf2, bf2, pns, dst, kSR, kD, kD);
  }
}